// round 9
// baseline (speedup 1.0000x reference)
#include <cuda_runtime.h>

#define FULL 0xffffffffu

constexpr int C    = 128;
constexpr int NMAX = 262144;

// ---------------- device scratch (static: no allocation allowed) ------------
__device__ float    g_loss[NMAX];
__device__ float    g_corr[NMAX];          // corr value if masked, -1.0f sentinel otherwise
__device__ double   g_kl_part[32];
__device__ double   g_loss_part[32];
__device__ double   g_clean_sum;
__device__ double   g_corr_sum;
__device__ unsigned long long g_cnt;
__device__ unsigned g_h1[2048], g_h2[2048], g_h3[1024];
__device__ unsigned g_b1, g_b12, g_key;
__device__ int      g_krem;
__device__ int      g_t64;                 // 1 if targets are int64

// float -> order-preserving uint (losses are >=0, but handle sign generally)
__device__ __forceinline__ unsigned orderf(float f) {
    unsigned u = __float_as_uint(f);
    return (u & 0x80000000u) ? ~u : (u | 0x80000000u);
}

__device__ __forceinline__ int num_remember_dev(int epoch, int n) {
    // match python: INCREMENT = 0.5/100; int(truncation)
    double fr = fmin(0.5, (0.5 / 100.0) * (double)epoch);
    double rr = fmax(0.5, 1.0 - fr);
    return (int)(rr * (double)n);
}

// ---------------- K0: zero accumulators + detect int64 targets --------------
__global__ void k_init(const void* __restrict__ targ, int n) {
    int t = threadIdx.x;
    for (int i = t; i < 2048; i += 1024) g_h1[i] = 0;
    for (int i = t; i < 2048; i += 1024) g_h2[i] = 0;
    for (int i = t; i < 1024; i += 1024) g_h3[i] = 0;
    if (t < 32) { g_kl_part[t] = 0.0; g_loss_part[t] = 0.0; }
    if (t == 0) {
        g_clean_sum = 0.0; g_corr_sum = 0.0; g_cnt = 0ull;
        g_b1 = 0; g_b12 = 0; g_key = 0; g_krem = 1;
        // int64 detection: targets < C=128, so for int64 every odd 32-bit word is 0.
        const int* w = (const int*)targ;
        int nchk = (n >= 64) ? 32 : (n / 2);
        bool t64 = (nchk > 0);
        for (int j = 0; j < nchk; j++)
            if (w[2 * j + 1] != 0) { t64 = false; break; }
        g_t64 = t64 ? 1 : 0;
    }
}

// ---------------- K1: fused per-row softmax statistics ----------------------
// one warp per row; both rows (128 f32 each) held in registers -> single DRAM read
__global__ __launch_bounds__(256) void k_main(const float* __restrict__ y1,
                                              const float* __restrict__ y2,
                                              const void*  __restrict__ targ,
                                              int n) {
    int row  = blockIdx.x * 8 + (threadIdx.x >> 5);
    int lane = threadIdx.x & 31;
    __shared__ double skl[8], sls[8];

    double kl_i = 0.0, lossd = 0.0;

    if (row < n) {
        const float4 av = ((const float4*)(y1 + (size_t)row * C))[lane];
        const float4 bv = ((const float4*)(y2 + (size_t)row * C))[lane];
        float a[4] = {av.x, av.y, av.z, av.w};
        float b[4] = {bv.x, bv.y, bv.z, bv.w};

        // per-lane max + first-occurrence argmax
        float m1 = a[0], m2 = b[0];
        int   i1 = 0,   i2 = 0;
#pragma unroll
        for (int j = 1; j < 4; j++) {
            if (a[j] > m1) { m1 = a[j]; i1 = j; }
            if (b[j] > m2) { m2 = b[j]; i2 = j; }
        }
        i1 += lane * 4; i2 += lane * 4;

        // warp all-reduce (max, min-index) — associative/commutative/idempotent
#pragma unroll
        for (int off = 16; off; off >>= 1) {
            float om = __shfl_xor_sync(FULL, m1, off);
            int   oi = __shfl_xor_sync(FULL, i1, off);
            if (om > m1 || (om == m1 && oi < i1)) { m1 = om; i1 = oi; }
            float pm = __shfl_xor_sync(FULL, m2, off);
            int   pi = __shfl_xor_sync(FULL, i2, off);
            if (pm > m2 || (pm == m2 && pi < i2)) { m2 = pm; i2 = pi; }
        }

        // exp-sums and KL cross terms:  kl_i = W1/s1 + W2/s2  (lse terms cancel)
        float s1 = 0.f, s2 = 0.f, w1 = 0.f, w2 = 0.f;
#pragma unroll
        for (int j = 0; j < 4; j++) {
            float d  = a[j] - b[j];
            float e1 = __expf(a[j] - m1);
            float e2 = __expf(b[j] - m2);
            s1 += e1; s2 += e2;
            w1 += e1 * d; w2 -= e2 * d;
        }
#pragma unroll
        for (int off = 16; off; off >>= 1) {
            s1 += __shfl_xor_sync(FULL, s1, off);
            s2 += __shfl_xor_sync(FULL, s2, off);
            w1 += __shfl_xor_sync(FULL, w1, off);
            w2 += __shfl_xor_sync(FULL, w2, off);
        }

        // target logits (t uniform across warp)
        int t;
        if (g_t64) t = (int)(((const long long*)targ)[row]);
        else       t = ((const int*)targ)[row];
        int ts = t & 3, tl = t >> 2;
        float ca  = (ts == 0) ? a[0] : (ts == 1) ? a[1] : (ts == 2) ? a[2] : a[3];
        float cb  = (ts == 0) ? b[0] : (ts == 1) ? b[1] : (ts == 2) ? b[2] : b[3];
        float y1t = __shfl_sync(FULL, ca, tl);
        float y2t = __shfl_sync(FULL, cb, tl);

        // y2 at pred1 (= argmax of y1)
        int ps = i1 & 3, pl = i1 >> 2;
        float cbp = (ps == 0) ? b[0] : (ps == 1) ? b[1] : (ps == 2) ? b[2] : b[3];
        float y2p = __shfl_sync(FULL, cbp, pl);

        float ls1 = __logf(s1), ls2 = __logf(s2);
        float lse1 = m1 + ls1, lse2 = m2 + ls2;

        float loss = (lse1 - y1t) + (lse2 - y2t);
        lossd = (double)loss;
        kl_i  = (double)(w1 / s1) + (double)(w2 / s2);

        // conf1 = 1/s1, conf2 = 1/s2; ce1 = log s1; ce2 = lse2 - y2[pred1]
        float pc   = 1.0f / (s1 * s2);
        float corr = -1.0f;                       // sentinel = not masked
        if (i1 == i2 && pc > 0.5f)
            corr = sqrtf(pc) * (ls1 + (lse2 - y2p));

        if (lane == 0) {
            g_loss[row] = loss;
            g_corr[row] = corr;
        }
    }

    int wid = threadIdx.x >> 5;
    if (lane == 0) { skl[wid] = kl_i; sls[wid] = lossd; }
    __syncthreads();
    if (threadIdx.x == 0) {
        double ak = 0.0, al = 0.0;
#pragma unroll
        for (int w = 0; w < 8; w++) { ak += skl[w]; al += sls[w]; }
        int slot = blockIdx.x & 31;
        atomicAdd(&g_kl_part[slot], ak);
        atomicAdd(&g_loss_part[slot], al);
    }
}

// ---------------- radix select: 11 + 11 + 10 bits ---------------------------
__global__ __launch_bounds__(256) void k_hist1(int n) {
    __shared__ unsigned sh[2048];
    for (int i = threadIdx.x; i < 2048; i += blockDim.x) sh[i] = 0;
    __syncthreads();
    int stride = blockDim.x * gridDim.x;
    for (int i = blockIdx.x * blockDim.x + threadIdx.x; i < n; i += stride)
        atomicAdd(&sh[orderf(g_loss[i]) >> 21], 1u);
    __syncthreads();
    for (int i = threadIdx.x; i < 2048; i += blockDim.x)
        if (sh[i]) atomicAdd(&g_h1[i], sh[i]);
}

__global__ void k_scan1(const void* __restrict__ ep, int n) {
    int epoch = *((const int*)ep);                 // works for int32 and LE int64
    int k = num_remember_dev(epoch, n);
    if (k < 1) k = 1;
    unsigned cum = 0;
    for (int b = 0; b < 2048; b++) {
        unsigned c = g_h1[b];
        if (cum + c >= (unsigned)k) { g_b1 = (unsigned)b; g_krem = k - (int)cum; return; }
        cum += c;
    }
    g_b1 = 2047u; g_krem = 1;
}

__global__ __launch_bounds__(256) void k_hist2(int n) {
    __shared__ unsigned sh[2048];
    for (int i = threadIdx.x; i < 2048; i += blockDim.x) sh[i] = 0;
    __syncthreads();
    unsigned b1 = g_b1;
    int stride = blockDim.x * gridDim.x;
    for (int i = blockIdx.x * blockDim.x + threadIdx.x; i < n; i += stride) {
        unsigned u = orderf(g_loss[i]);
        if ((u >> 21) == b1) atomicAdd(&sh[(u >> 10) & 2047u], 1u);
    }
    __syncthreads();
    for (int i = threadIdx.x; i < 2048; i += blockDim.x)
        if (sh[i]) atomicAdd(&g_h2[i], sh[i]);
}

__global__ void k_scan2() {
    int k = g_krem;
    unsigned cum = 0;
    for (int b = 0; b < 2048; b++) {
        unsigned c = g_h2[b];
        if (cum + c >= (unsigned)k) {
            g_b12 = (g_b1 << 11) | (unsigned)b;
            g_krem = k - (int)cum;
            return;
        }
        cum += c;
    }
    g_b12 = (g_b1 << 11) | 2047u; g_krem = 1;
}

__global__ __launch_bounds__(256) void k_hist3(int n) {
    __shared__ unsigned sh[1024];
    for (int i = threadIdx.x; i < 1024; i += blockDim.x) sh[i] = 0;
    __syncthreads();
    unsigned b12 = g_b12;
    int stride = blockDim.x * gridDim.x;
    for (int i = blockIdx.x * blockDim.x + threadIdx.x; i < n; i += stride) {
        unsigned u = orderf(g_loss[i]);
        if ((u >> 10) == b12) atomicAdd(&sh[u & 1023u], 1u);
    }
    __syncthreads();
    for (int i = threadIdx.x; i < 1024; i += blockDim.x)
        if (sh[i]) atomicAdd(&g_h3[i], sh[i]);
}

__global__ void k_scan3() {
    int k = g_krem;
    unsigned cum = 0;
    for (int b = 0; b < 1024; b++) {
        unsigned c = g_h3[b];
        if (cum + c >= (unsigned)k) { g_key = (g_b12 << 10) | (unsigned)b; return; }
        cum += c;
    }
    g_key = (g_b12 << 10) | 1023u;
}

// ---------------- K8: clean sum + noisy masked correction -------------------
__global__ __launch_bounds__(256) void k_reduce(int n) {
    unsigned key = g_key;
    double cs = 0.0, crs = 0.0;
    unsigned long long cnt = 0ull;
    int stride = blockDim.x * gridDim.x;
    for (int i = blockIdx.x * blockDim.x + threadIdx.x; i < n; i += stride) {
        float L = g_loss[i];
        unsigned u = orderf(L);
        if (u <= key) {
            cs += (double)L;
        } else {
            float c = g_corr[i];
            if (c >= 0.0f) { crs += (double)c; cnt++; }
        }
    }
#pragma unroll
    for (int off = 16; off; off >>= 1) {
        cs  += __shfl_xor_sync(FULL, cs, off);
        crs += __shfl_xor_sync(FULL, crs, off);
        cnt += __shfl_xor_sync(FULL, cnt, off);
    }
    __shared__ double sc[8], sr[8];
    __shared__ unsigned long long sn[8];
    int lane = threadIdx.x & 31, wid = threadIdx.x >> 5;
    if (lane == 0) { sc[wid] = cs; sr[wid] = crs; sn[wid] = cnt; }
    __syncthreads();
    if (threadIdx.x == 0) {
        double a = 0.0, b = 0.0; unsigned long long c = 0ull;
#pragma unroll
        for (int w = 0; w < 8; w++) { a += sc[w]; b += sr[w]; c += sn[w]; }
        atomicAdd(&g_clean_sum, a);
        atomicAdd(&g_corr_sum, b);
        atomicAdd(&g_cnt, c);
    }
}

// ---------------- K9: finalize ----------------------------------------------
__global__ void k_final(const void* __restrict__ ep, int n, float* __restrict__ out) {
    int epoch = *((const int*)ep);
    double klsum = 0.0, lsum = 0.0;
    for (int i = 0; i < 32; i++) { klsum += g_kl_part[i]; lsum += g_loss_part[i]; }
    double res;
    if (epoch == 0) {
        res = lsum / (double)n;
    } else {
        int k = num_remember_dev(epoch, n);
        if (k < 1) k = 1;
        double clean = g_clean_sum / (double)k;
        double corrm = (g_cnt > 0ull) ? (g_corr_sum / (double)g_cnt) : 0.0;
        res = clean + corrm + 0.1 * (klsum / (double)n);
    }
    *out = (float)res;
}

// ---------------- launch ------------------------------------------------------
extern "C" void kernel_launch(void* const* d_in, const int* in_sizes, int n_in,
                              void* d_out, int out_size) {
    const float* y1   = (const float*)d_in[0];
    const float* y2   = (const float*)d_in[1];
    const void*  targ = d_in[2];
    const void*  ep   = d_in[3];
    int n = in_sizes[0] / C;

    k_init<<<1, 1024>>>(targ, n);
    k_main<<<(n + 7) / 8, 256>>>(y1, y2, targ, n);
    k_hist1<<<256, 256>>>(n);
    k_scan1<<<1, 1>>>(ep, n);
    k_hist2<<<256, 256>>>(n);
    k_scan2<<<1, 1>>>();
    k_hist3<<<256, 256>>>(n);
    k_scan3<<<1, 1>>>();
    k_reduce<<<256, 256>>>(n);
    k_final<<<1, 1>>>(ep, n, (float*)d_out);
}

// round 10
// speedup vs baseline: 1.0055x; 1.0055x over previous
#include <cuda_runtime.h>

#define FULL 0xffffffffu

constexpr int C    = 128;
constexpr int NMAX = 262144;

// ---------------- device scratch (static: no allocation allowed) ------------
__device__ float    g_loss[NMAX];
__device__ float    g_corr[NMAX];          // corr value if masked, -1.0f sentinel otherwise
__device__ double   g_kl_part[32];
__device__ double   g_loss_part[32];
__device__ double   g_clean_sum;
__device__ double   g_corr_sum;
__device__ unsigned long long g_cnt;
__device__ unsigned g_h1[2048], g_h2[2048], g_h3[1024];
__device__ unsigned g_b1, g_b12, g_key;
__device__ int      g_krem;
__device__ int      g_t64;                 // 1 if targets are int64

// float -> order-preserving uint (losses are >=0, but handle sign generally)
__device__ __forceinline__ unsigned orderf(float f) {
    unsigned u = __float_as_uint(f);
    return (u & 0x80000000u) ? ~u : (u | 0x80000000u);
}

__device__ __forceinline__ int num_remember_dev(int epoch, int n) {
    // match python: INCREMENT = 0.5/100; int(truncation)
    double fr = fmin(0.5, (0.5 / 100.0) * (double)epoch);
    double rr = fmax(0.5, 1.0 - fr);
    return (int)(rr * (double)n);
}

// ---------------- K0: zero accumulators + detect int64 targets --------------
__global__ void k_init(const void* __restrict__ targ, int n) {
    int t = threadIdx.x;
    for (int i = t; i < 2048; i += 1024) g_h1[i] = 0;
    for (int i = t; i < 2048; i += 1024) g_h2[i] = 0;
    for (int i = t; i < 1024; i += 1024) g_h3[i] = 0;
    if (t < 32) { g_kl_part[t] = 0.0; g_loss_part[t] = 0.0; }
    if (t == 0) {
        g_clean_sum = 0.0; g_corr_sum = 0.0; g_cnt = 0ull;
        g_b1 = 0; g_b12 = 0; g_key = 0; g_krem = 1;
        // int64 detection: targets < C=128, so for int64 every odd 32-bit word is 0.
        const int* w = (const int*)targ;
        int nchk = (n >= 64) ? 32 : (n / 2);
        bool t64 = (nchk > 0);
        for (int j = 0; j < nchk; j++)
            if (w[2 * j + 1] != 0) { t64 = false; break; }
        g_t64 = t64 ? 1 : 0;
    }
}

// ---------------- K1: fused per-row softmax statistics ----------------------
// one warp per row; both rows (128 f32 each) held in registers -> single DRAM read
__global__ __launch_bounds__(256) void k_main(const float* __restrict__ y1,
                                              const float* __restrict__ y2,
                                              const void*  __restrict__ targ,
                                              int n) {
    int row  = blockIdx.x * 8 + (threadIdx.x >> 5);
    int lane = threadIdx.x & 31;
    __shared__ double skl[8], sls[8];

    double kl_i = 0.0, lossd = 0.0;

    if (row < n) {
        const float4 av = ((const float4*)(y1 + (size_t)row * C))[lane];
        const float4 bv = ((const float4*)(y2 + (size_t)row * C))[lane];
        float a[4] = {av.x, av.y, av.z, av.w};
        float b[4] = {bv.x, bv.y, bv.z, bv.w};

        // per-lane max + first-occurrence argmax
        float m1 = a[0], m2 = b[0];
        int   i1 = 0,   i2 = 0;
#pragma unroll
        for (int j = 1; j < 4; j++) {
            if (a[j] > m1) { m1 = a[j]; i1 = j; }
            if (b[j] > m2) { m2 = b[j]; i2 = j; }
        }
        i1 += lane * 4; i2 += lane * 4;

        // warp all-reduce (max, min-index) — associative/commutative/idempotent
#pragma unroll
        for (int off = 16; off; off >>= 1) {
            float om = __shfl_xor_sync(FULL, m1, off);
            int   oi = __shfl_xor_sync(FULL, i1, off);
            if (om > m1 || (om == m1 && oi < i1)) { m1 = om; i1 = oi; }
            float pm = __shfl_xor_sync(FULL, m2, off);
            int   pi = __shfl_xor_sync(FULL, i2, off);
            if (pm > m2 || (pm == m2 && pi < i2)) { m2 = pm; i2 = pi; }
        }

        // exp-sums and KL cross terms:  kl_i = W1/s1 + W2/s2  (lse terms cancel)
        float s1 = 0.f, s2 = 0.f, w1 = 0.f, w2 = 0.f;
#pragma unroll
        for (int j = 0; j < 4; j++) {
            float d  = a[j] - b[j];
            float e1 = __expf(a[j] - m1);
            float e2 = __expf(b[j] - m2);
            s1 += e1; s2 += e2;
            w1 += e1 * d; w2 -= e2 * d;
        }
#pragma unroll
        for (int off = 16; off; off >>= 1) {
            s1 += __shfl_xor_sync(FULL, s1, off);
            s2 += __shfl_xor_sync(FULL, s2, off);
            w1 += __shfl_xor_sync(FULL, w1, off);
            w2 += __shfl_xor_sync(FULL, w2, off);
        }

        // target logits (t uniform across warp)
        int t;
        if (g_t64) t = (int)(((const long long*)targ)[row]);
        else       t = ((const int*)targ)[row];
        int ts = t & 3, tl = t >> 2;
        float ca  = (ts == 0) ? a[0] : (ts == 1) ? a[1] : (ts == 2) ? a[2] : a[3];
        float cb  = (ts == 0) ? b[0] : (ts == 1) ? b[1] : (ts == 2) ? b[2] : b[3];
        float y1t = __shfl_sync(FULL, ca, tl);
        float y2t = __shfl_sync(FULL, cb, tl);

        // y2 at pred1 (= argmax of y1)
        int ps = i1 & 3, pl = i1 >> 2;
        float cbp = (ps == 0) ? b[0] : (ps == 1) ? b[1] : (ps == 2) ? b[2] : b[3];
        float y2p = __shfl_sync(FULL, cbp, pl);

        float ls1 = __logf(s1), ls2 = __logf(s2);
        float lse1 = m1 + ls1, lse2 = m2 + ls2;

        float loss = (lse1 - y1t) + (lse2 - y2t);
        lossd = (double)loss;
        kl_i  = (double)(w1 / s1) + (double)(w2 / s2);

        // conf1 = 1/s1, conf2 = 1/s2; ce1 = log s1; ce2 = lse2 - y2[pred1]
        float pc   = 1.0f / (s1 * s2);
        float corr = -1.0f;                       // sentinel = not masked
        if (i1 == i2 && pc > 0.5f)
            corr = sqrtf(pc) * (ls1 + (lse2 - y2p));

        if (lane == 0) {
            g_loss[row] = loss;
            g_corr[row] = corr;
        }
    }

    int wid = threadIdx.x >> 5;
    if (lane == 0) { skl[wid] = kl_i; sls[wid] = lossd; }
    __syncthreads();
    if (threadIdx.x == 0) {
        double ak = 0.0, al = 0.0;
#pragma unroll
        for (int w = 0; w < 8; w++) { ak += skl[w]; al += sls[w]; }
        int slot = blockIdx.x & 31;
        atomicAdd(&g_kl_part[slot], ak);
        atomicAdd(&g_loss_part[slot], al);
    }
}

// ---------------- radix select: 11 + 11 + 10 bits ---------------------------
__global__ __launch_bounds__(256) void k_hist1(int n) {
    __shared__ unsigned sh[2048];
    for (int i = threadIdx.x; i < 2048; i += blockDim.x) sh[i] = 0;
    __syncthreads();
    int stride = blockDim.x * gridDim.x;
    for (int i = blockIdx.x * blockDim.x + threadIdx.x; i < n; i += stride)
        atomicAdd(&sh[orderf(g_loss[i]) >> 21], 1u);
    __syncthreads();
    for (int i = threadIdx.x; i < 2048; i += blockDim.x)
        if (sh[i]) atomicAdd(&g_h1[i], sh[i]);
}

__global__ void k_scan1(const void* __restrict__ ep, int n) {
    int epoch = *((const int*)ep);                 // works for int32 and LE int64
    int k = num_remember_dev(epoch, n);
    if (k < 1) k = 1;
    unsigned cum = 0;
    for (int b = 0; b < 2048; b++) {
        unsigned c = g_h1[b];
        if (cum + c >= (unsigned)k) { g_b1 = (unsigned)b; g_krem = k - (int)cum; return; }
        cum += c;
    }
    g_b1 = 2047u; g_krem = 1;
}

__global__ __launch_bounds__(256) void k_hist2(int n) {
    __shared__ unsigned sh[2048];
    for (int i = threadIdx.x; i < 2048; i += blockDim.x) sh[i] = 0;
    __syncthreads();
    unsigned b1 = g_b1;
    int stride = blockDim.x * gridDim.x;
    for (int i = blockIdx.x * blockDim.x + threadIdx.x; i < n; i += stride) {
        unsigned u = orderf(g_loss[i]);
        if ((u >> 21) == b1) atomicAdd(&sh[(u >> 10) & 2047u], 1u);
    }
    __syncthreads();
    for (int i = threadIdx.x; i < 2048; i += blockDim.x)
        if (sh[i]) atomicAdd(&g_h2[i], sh[i]);
}

__global__ void k_scan2() {
    int k = g_krem;
    unsigned cum = 0;
    for (int b = 0; b < 2048; b++) {
        unsigned c = g_h2[b];
        if (cum + c >= (unsigned)k) {
            g_b12 = (g_b1 << 11) | (unsigned)b;
            g_krem = k - (int)cum;
            return;
        }
        cum += c;
    }
    g_b12 = (g_b1 << 11) | 2047u; g_krem = 1;
}

__global__ __launch_bounds__(256) void k_hist3(int n) {
    __shared__ unsigned sh[1024];
    for (int i = threadIdx.x; i < 1024; i += blockDim.x) sh[i] = 0;
    __syncthreads();
    unsigned b12 = g_b12;
    int stride = blockDim.x * gridDim.x;
    for (int i = blockIdx.x * blockDim.x + threadIdx.x; i < n; i += stride) {
        unsigned u = orderf(g_loss[i]);
        if ((u >> 10) == b12) atomicAdd(&sh[u & 1023u], 1u);
    }
    __syncthreads();
    for (int i = threadIdx.x; i < 1024; i += blockDim.x)
        if (sh[i]) atomicAdd(&g_h3[i], sh[i]);
}

__global__ void k_scan3() {
    int k = g_krem;
    unsigned cum = 0;
    for (int b = 0; b < 1024; b++) {
        unsigned c = g_h3[b];
        if (cum + c >= (unsigned)k) { g_key = (g_b12 << 10) | (unsigned)b; return; }
        cum += c;
    }
    g_key = (g_b12 << 10) | 1023u;
}

// ---------------- K8: clean sum + noisy masked correction -------------------
__global__ __launch_bounds__(256) void k_reduce(int n) {
    unsigned key = g_key;
    double cs = 0.0, crs = 0.0;
    unsigned long long cnt = 0ull;
    int stride = blockDim.x * gridDim.x;
    for (int i = blockIdx.x * blockDim.x + threadIdx.x; i < n; i += stride) {
        float L = g_loss[i];
        unsigned u = orderf(L);
        if (u <= key) {
            cs += (double)L;
        } else {
            float c = g_corr[i];
            if (c >= 0.0f) { crs += (double)c; cnt++; }
        }
    }
#pragma unroll
    for (int off = 16; off; off >>= 1) {
        cs  += __shfl_xor_sync(FULL, cs, off);
        crs += __shfl_xor_sync(FULL, crs, off);
        cnt += __shfl_xor_sync(FULL, cnt, off);
    }
    __shared__ double sc[8], sr[8];
    __shared__ unsigned long long sn[8];
    int lane = threadIdx.x & 31, wid = threadIdx.x >> 5;
    if (lane == 0) { sc[wid] = cs; sr[wid] = crs; sn[wid] = cnt; }
    __syncthreads();
    if (threadIdx.x == 0) {
        double a = 0.0, b = 0.0; unsigned long long c = 0ull;
#pragma unroll
        for (int w = 0; w < 8; w++) { a += sc[w]; b += sr[w]; c += sn[w]; }
        atomicAdd(&g_clean_sum, a);
        atomicAdd(&g_corr_sum, b);
        atomicAdd(&g_cnt, c);
    }
}

// ---------------- K9: finalize ----------------------------------------------
__global__ void k_final(const void* __restrict__ ep, int n, float* __restrict__ out) {
    int epoch = *((const int*)ep);
    double klsum = 0.0, lsum = 0.0;
    for (int i = 0; i < 32; i++) { klsum += g_kl_part[i]; lsum += g_loss_part[i]; }
    double res;
    if (epoch == 0) {
        res = lsum / (double)n;
    } else {
        int k = num_remember_dev(epoch, n);
        if (k < 1) k = 1;
        double clean = g_clean_sum / (double)k;
        double corrm = (g_cnt > 0ull) ? (g_corr_sum / (double)g_cnt) : 0.0;
        res = clean + corrm + 0.1 * (klsum / (double)n);
    }
    *out = (float)res;
}

// ---------------- launch ------------------------------------------------------
extern "C" void kernel_launch(void* const* d_in, const int* in_sizes, int n_in,
                              void* d_out, int out_size) {
    const float* y1   = (const float*)d_in[0];
    const float* y2   = (const float*)d_in[1];
    const void*  targ = d_in[2];
    const void*  ep   = d_in[3];
    int n = in_sizes[0] / C;

    k_init<<<1, 1024>>>(targ, n);
    k_main<<<(n + 7) / 8, 256>>>(y1, y2, targ, n);
    k_hist1<<<256, 256>>>(n);
    k_scan1<<<1, 1>>>(ep, n);
    k_hist2<<<256, 256>>>(n);
    k_scan2<<<1, 1>>>();
    k_hist3<<<256, 256>>>(n);
    k_scan3<<<1, 1>>>();
    k_reduce<<<256, 256>>>(n);
    k_final<<<1, 1>>>(ep, n, (float*)d_out);
}

// round 11
// speedup vs baseline: 1.3510x; 1.3436x over previous
#include <cuda_runtime.h>

#define FULL 0xffffffffu

constexpr int C    = 128;
constexpr int NMAX = 262144;

// ---------------- device scratch (static: no allocation allowed) ------------
__device__ float    g_loss[NMAX];
__device__ float    g_corr[NMAX];          // corr value if masked, -1.0f sentinel otherwise
__device__ double   g_kl_part[32];
__device__ double   g_loss_part[32];
__device__ double   g_clean_sum;
__device__ double   g_corr_sum;
__device__ unsigned long long g_cnt;
__device__ unsigned g_h1[2048], g_h2[2048], g_h3[1024];
__device__ unsigned g_b1, g_b12, g_key;
__device__ int      g_krem;
__device__ int      g_t64;                 // 1 if targets are int64
__device__ unsigned g_tick1, g_tick2, g_tick3, g_tick4;

// float -> order-preserving uint
__device__ __forceinline__ unsigned orderf(float f) {
    unsigned u = __float_as_uint(f);
    return (u & 0x80000000u) ? ~u : (u | 0x80000000u);
}

__device__ __forceinline__ int num_remember_dev(int epoch, int n) {
    double fr = fmin(0.5, (0.5 / 100.0) * (double)epoch);
    double rr = fmax(0.5, 1.0 - fr);
    return (int)(rr * (double)n);
}

// parallel "find bucket where cumsum crosses k" — call with 256 threads,
// NB buckets (multiple of 256). Exactly one thread hits the crossing.
template <int NB>
__device__ __forceinline__ void find_bucket(const unsigned* __restrict__ hist, int k,
                                            unsigned* out_b, int* out_krem) {
    __shared__ unsigned csum[256];
    constexpr int PER = NB / 256;
    int t = threadIdx.x;
    unsigned loc[PER];
    unsigned s = 0;
#pragma unroll
    for (int j = 0; j < PER; j++) { loc[j] = hist[t * PER + j]; s += loc[j]; }
    csum[t] = s;
    __syncthreads();
    // inclusive Hillis-Steele scan over 256 chunk sums
#pragma unroll
    for (int off = 1; off < 256; off <<= 1) {
        unsigned v = (t >= off) ? csum[t - off] : 0u;
        __syncthreads();
        csum[t] += v;
        __syncthreads();
    }
    unsigned prev = (t == 0) ? 0u : csum[t - 1];
    if (prev < (unsigned)k && csum[t] >= (unsigned)k) {
        unsigned cum = prev;
#pragma unroll
        for (int j = 0; j < PER; j++) {
            unsigned c = loc[j];
            if (cum + c >= (unsigned)k) { *out_b = (unsigned)(t * PER + j); *out_krem = k - (int)cum; break; }
            cum += c;
        }
    }
}

// returns true for the last block to arrive (block-uniform)
__device__ __forceinline__ bool last_block(unsigned* tick) {
    __threadfence();
    __shared__ bool isLast;
    if (threadIdx.x == 0) isLast = (atomicAdd(tick, 1u) == gridDim.x - 1);
    __syncthreads();
    return isLast;
}

// ---------------- K0: zero accumulators + detect int64 targets --------------
__global__ void k_init(const void* __restrict__ targ, int n) {
    int t = threadIdx.x;
    for (int i = t; i < 2048; i += 1024) g_h1[i] = 0;
    for (int i = t; i < 2048; i += 1024) g_h2[i] = 0;
    for (int i = t; i < 1024; i += 1024) g_h3[i] = 0;
    if (t < 32) { g_kl_part[t] = 0.0; g_loss_part[t] = 0.0; }
    if (t == 0) {
        g_clean_sum = 0.0; g_corr_sum = 0.0; g_cnt = 0ull;
        g_b1 = 0; g_b12 = 0; g_key = 0; g_krem = 1;
        g_tick1 = 0; g_tick2 = 0; g_tick3 = 0; g_tick4 = 0;
        const int* w = (const int*)targ;
        int nchk = (n >= 64) ? 32 : (n / 2);
        bool t64 = (nchk > 0);
        for (int j = 0; j < nchk; j++)
            if (w[2 * j + 1] != 0) { t64 = false; break; }
        g_t64 = t64 ? 1 : 0;
    }
}

// ---------------- K1: fused per-row stats + hist1 + (last block) scan1 ------
__global__ __launch_bounds__(256) void k_main(const float* __restrict__ y1,
                                              const float* __restrict__ y2,
                                              const void*  __restrict__ targ,
                                              const void*  __restrict__ ep,
                                              int n) {
    int row  = blockIdx.x * 8 + (threadIdx.x >> 5);
    int lane = threadIdx.x & 31;
    __shared__ double skl[8], sls[8];

    double kl_i = 0.0, lossd = 0.0;

    if (row < n) {
        const float4 av = ((const float4*)(y1 + (size_t)row * C))[lane];
        const float4 bv = ((const float4*)(y2 + (size_t)row * C))[lane];
        float a[4] = {av.x, av.y, av.z, av.w};
        float b[4] = {bv.x, bv.y, bv.z, bv.w};

        float m1 = a[0], m2 = b[0];
        int   i1 = 0,   i2 = 0;
#pragma unroll
        for (int j = 1; j < 4; j++) {
            if (a[j] > m1) { m1 = a[j]; i1 = j; }
            if (b[j] > m2) { m2 = b[j]; i2 = j; }
        }
        i1 += lane * 4; i2 += lane * 4;

#pragma unroll
        for (int off = 16; off; off >>= 1) {
            float om = __shfl_xor_sync(FULL, m1, off);
            int   oi = __shfl_xor_sync(FULL, i1, off);
            if (om > m1 || (om == m1 && oi < i1)) { m1 = om; i1 = oi; }
            float pm = __shfl_xor_sync(FULL, m2, off);
            int   pi = __shfl_xor_sync(FULL, i2, off);
            if (pm > m2 || (pm == m2 && pi < i2)) { m2 = pm; i2 = pi; }
        }

        float s1 = 0.f, s2 = 0.f, w1 = 0.f, w2 = 0.f;
#pragma unroll
        for (int j = 0; j < 4; j++) {
            float d  = a[j] - b[j];
            float e1 = __expf(a[j] - m1);
            float e2 = __expf(b[j] - m2);
            s1 += e1; s2 += e2;
            w1 += e1 * d; w2 -= e2 * d;
        }
#pragma unroll
        for (int off = 16; off; off >>= 1) {
            s1 += __shfl_xor_sync(FULL, s1, off);
            s2 += __shfl_xor_sync(FULL, s2, off);
            w1 += __shfl_xor_sync(FULL, w1, off);
            w2 += __shfl_xor_sync(FULL, w2, off);
        }

        int t;
        if (g_t64) t = (int)(((const long long*)targ)[row]);
        else       t = ((const int*)targ)[row];
        int ts = t & 3, tl = t >> 2;
        float ca  = (ts == 0) ? a[0] : (ts == 1) ? a[1] : (ts == 2) ? a[2] : a[3];
        float cb  = (ts == 0) ? b[0] : (ts == 1) ? b[1] : (ts == 2) ? b[2] : b[3];
        float y1t = __shfl_sync(FULL, ca, tl);
        float y2t = __shfl_sync(FULL, cb, tl);

        int ps = i1 & 3, pl = i1 >> 2;
        float cbp = (ps == 0) ? b[0] : (ps == 1) ? b[1] : (ps == 2) ? b[2] : b[3];
        float y2p = __shfl_sync(FULL, cbp, pl);

        float ls1 = __logf(s1), ls2 = __logf(s2);
        float lse1 = m1 + ls1, lse2 = m2 + ls2;

        float loss = (lse1 - y1t) + (lse2 - y2t);
        lossd = (double)loss;
        kl_i  = (double)(w1 / s1) + (double)(w2 / s2);

        float pc   = 1.0f / (s1 * s2);
        float corr = -1.0f;
        if (i1 == i2 && pc > 0.5f)
            corr = sqrtf(pc) * (ls1 + (lse2 - y2p));

        if (lane == 0) {
            g_loss[row] = loss;
            g_corr[row] = corr;
            atomicAdd(&g_h1[orderf(loss) >> 21], 1u);   // fused hist1
        }
    }

    int wid = threadIdx.x >> 5;
    if (lane == 0) { skl[wid] = kl_i; sls[wid] = lossd; }
    __syncthreads();
    if (threadIdx.x == 0) {
        double ak = 0.0, al = 0.0;
#pragma unroll
        for (int w = 0; w < 8; w++) { ak += skl[w]; al += sls[w]; }
        int slot = blockIdx.x & 31;
        atomicAdd(&g_kl_part[slot], ak);
        atomicAdd(&g_loss_part[slot], al);
    }

    // last block performs scan1 (256 threads, parallel)
    if (last_block(&g_tick1)) {
        int epoch = *((const int*)ep);
        int k = num_remember_dev(epoch, n);
        if (k < 1) k = 1;
        g_krem = 1; g_b1 = 2047u;          // fallback
        __syncthreads();
        find_bucket<2048>(g_h1, k, &g_b1, &g_krem);
    }
}

// ---------------- hist2 + (last block) scan2 --------------------------------
__global__ __launch_bounds__(256) void k_hist2(int n) {
    __shared__ unsigned sh[2048];
    for (int i = threadIdx.x; i < 2048; i += blockDim.x) sh[i] = 0;
    __syncthreads();
    unsigned b1 = g_b1;
    int stride = blockDim.x * gridDim.x;
    for (int i = blockIdx.x * blockDim.x + threadIdx.x; i < n; i += stride) {
        unsigned u = orderf(g_loss[i]);
        if ((u >> 21) == b1) atomicAdd(&sh[(u >> 10) & 2047u], 1u);
    }
    __syncthreads();
    for (int i = threadIdx.x; i < 2048; i += blockDim.x)
        if (sh[i]) atomicAdd(&g_h2[i], sh[i]);

    if (last_block(&g_tick2)) {
        int k = g_krem;
        __shared__ unsigned sb; __shared__ int skr;
        if (threadIdx.x == 0) { sb = 2047u; skr = 1; }
        __syncthreads();
        find_bucket<2048>(g_h2, k, &sb, &skr);
        __syncthreads();
        if (threadIdx.x == 0) {
            g_b12 = (g_b1 << 11) | sb;
            g_krem = skr;
        }
    }
}

// ---------------- hist3 + (last block) scan3 --------------------------------
__global__ __launch_bounds__(256) void k_hist3(int n) {
    __shared__ unsigned sh[1024];
    for (int i = threadIdx.x; i < 1024; i += blockDim.x) sh[i] = 0;
    __syncthreads();
    unsigned b12 = g_b12;
    int stride = blockDim.x * gridDim.x;
    for (int i = blockIdx.x * blockDim.x + threadIdx.x; i < n; i += stride) {
        unsigned u = orderf(g_loss[i]);
        if ((u >> 10) == b12) atomicAdd(&sh[u & 1023u], 1u);
    }
    __syncthreads();
    for (int i = threadIdx.x; i < 1024; i += blockDim.x)
        if (sh[i]) atomicAdd(&g_h3[i], sh[i]);

    if (last_block(&g_tick3)) {
        int k = g_krem;
        __shared__ unsigned sb;
        if (threadIdx.x == 0) sb = 1023u;
        __syncthreads();
        int dummy;
        find_bucket<1024>(g_h3, k, &sb, &dummy);
        __syncthreads();
        if (threadIdx.x == 0) g_key = (g_b12 << 10) | sb;
    }
}

// ---------------- reduce + (last block) finalize ----------------------------
__global__ __launch_bounds__(256) void k_reduce(const void* __restrict__ ep,
                                                int n, float* __restrict__ out) {
    unsigned key = g_key;
    double cs = 0.0, crs = 0.0;
    unsigned long long cnt = 0ull;
    int stride = blockDim.x * gridDim.x;
    for (int i = blockIdx.x * blockDim.x + threadIdx.x; i < n; i += stride) {
        float L = g_loss[i];
        unsigned u = orderf(L);
        if (u <= key) {
            cs += (double)L;
        } else {
            float c = g_corr[i];
            if (c >= 0.0f) { crs += (double)c; cnt++; }
        }
    }
#pragma unroll
    for (int off = 16; off; off >>= 1) {
        cs  += __shfl_xor_sync(FULL, cs, off);
        crs += __shfl_xor_sync(FULL, crs, off);
        cnt += __shfl_xor_sync(FULL, cnt, off);
    }
    __shared__ double sc[8], sr[8];
    __shared__ unsigned long long sn[8];
    int lane = threadIdx.x & 31, wid = threadIdx.x >> 5;
    if (lane == 0) { sc[wid] = cs; sr[wid] = crs; sn[wid] = cnt; }
    __syncthreads();
    if (threadIdx.x == 0) {
        double a = 0.0, b = 0.0; unsigned long long c = 0ull;
#pragma unroll
        for (int w = 0; w < 8; w++) { a += sc[w]; b += sr[w]; c += sn[w]; }
        atomicAdd(&g_clean_sum, a);
        atomicAdd(&g_corr_sum, b);
        atomicAdd(&g_cnt, c);
    }

    if (last_block(&g_tick4)) {
        if (threadIdx.x == 0) {
            int epoch = *((const int*)ep);
            double klsum = 0.0, lsum = 0.0;
            for (int i = 0; i < 32; i++) { klsum += g_kl_part[i]; lsum += g_loss_part[i]; }
            double res;
            if (epoch == 0) {
                res = lsum / (double)n;
            } else {
                int k = num_remember_dev(epoch, n);
                if (k < 1) k = 1;
                double clean = g_clean_sum / (double)k;
                double corrm = (g_cnt > 0ull) ? (g_corr_sum / (double)g_cnt) : 0.0;
                res = clean + corrm + 0.1 * (klsum / (double)n);
            }
            *out = (float)res;
        }
    }
}

// ---------------- launch ------------------------------------------------------
extern "C" void kernel_launch(void* const* d_in, const int* in_sizes, int n_in,
                              void* d_out, int out_size) {
    const float* y1   = (const float*)d_in[0];
    const float* y2   = (const float*)d_in[1];
    const void*  targ = d_in[2];
    const void*  ep   = d_in[3];
    int n = in_sizes[0] / C;

    k_init<<<1, 1024>>>(targ, n);
    k_main<<<(n + 7) / 8, 256>>>(y1, y2, targ, ep, n);
    k_hist2<<<256, 256>>>(n);
    k_hist3<<<256, 256>>>(n);
    k_reduce<<<256, 256>>>(ep, n, (float*)d_out);
}

// round 12
// speedup vs baseline: 1.3526x; 1.0012x over previous
#include <cuda_runtime.h>

#define FULL 0xffffffffu

constexpr int C    = 128;
constexpr int NMAX = 262144;

// ---------------- device scratch (static: no allocation allowed) ------------
__device__ float    g_loss[NMAX];
__device__ float    g_corr[NMAX];          // corr value if masked, -1.0f sentinel otherwise
__device__ double   g_kl_part[32];
__device__ double   g_loss_part[32];
__device__ double   g_clean_sum;
__device__ double   g_corr_sum;
__device__ unsigned long long g_cnt;
__device__ unsigned g_h1[2048], g_h2[2048], g_h3[1024];
__device__ unsigned g_b1, g_b12, g_key;
__device__ int      g_krem;
__device__ int      g_t64;                 // 1 if targets are int64
__device__ unsigned g_tick1, g_tick2, g_tick3, g_tick4;

// float -> order-preserving uint
__device__ __forceinline__ unsigned orderf(float f) {
    unsigned u = __float_as_uint(f);
    return (u & 0x80000000u) ? ~u : (u | 0x80000000u);
}

__device__ __forceinline__ int num_remember_dev(int epoch, int n) {
    double fr = fmin(0.5, (0.5 / 100.0) * (double)epoch);
    double rr = fmax(0.5, 1.0 - fr);
    return (int)(rr * (double)n);
}

// parallel "find bucket where cumsum crosses k" — call with 256 threads,
// NB buckets (multiple of 256). Exactly one thread hits the crossing.
template <int NB>
__device__ __forceinline__ void find_bucket(const unsigned* __restrict__ hist, int k,
                                            unsigned* out_b, int* out_krem) {
    __shared__ unsigned csum[256];
    constexpr int PER = NB / 256;
    int t = threadIdx.x;
    unsigned loc[PER];
    unsigned s = 0;
#pragma unroll
    for (int j = 0; j < PER; j++) { loc[j] = hist[t * PER + j]; s += loc[j]; }
    csum[t] = s;
    __syncthreads();
    // inclusive Hillis-Steele scan over 256 chunk sums
#pragma unroll
    for (int off = 1; off < 256; off <<= 1) {
        unsigned v = (t >= off) ? csum[t - off] : 0u;
        __syncthreads();
        csum[t] += v;
        __syncthreads();
    }
    unsigned prev = (t == 0) ? 0u : csum[t - 1];
    if (prev < (unsigned)k && csum[t] >= (unsigned)k) {
        unsigned cum = prev;
#pragma unroll
        for (int j = 0; j < PER; j++) {
            unsigned c = loc[j];
            if (cum + c >= (unsigned)k) { *out_b = (unsigned)(t * PER + j); *out_krem = k - (int)cum; break; }
            cum += c;
        }
    }
}

// returns true for the last block to arrive (block-uniform)
__device__ __forceinline__ bool last_block(unsigned* tick) {
    __threadfence();
    __shared__ bool isLast;
    if (threadIdx.x == 0) isLast = (atomicAdd(tick, 1u) == gridDim.x - 1);
    __syncthreads();
    return isLast;
}

// ---------------- K0: zero accumulators + detect int64 targets --------------
__global__ void k_init(const void* __restrict__ targ, int n) {
    int t = threadIdx.x;
    for (int i = t; i < 2048; i += 1024) g_h1[i] = 0;
    for (int i = t; i < 2048; i += 1024) g_h2[i] = 0;
    for (int i = t; i < 1024; i += 1024) g_h3[i] = 0;
    if (t < 32) { g_kl_part[t] = 0.0; g_loss_part[t] = 0.0; }
    if (t == 0) {
        g_clean_sum = 0.0; g_corr_sum = 0.0; g_cnt = 0ull;
        g_b1 = 0; g_b12 = 0; g_key = 0; g_krem = 1;
        g_tick1 = 0; g_tick2 = 0; g_tick3 = 0; g_tick4 = 0;
        const int* w = (const int*)targ;
        int nchk = (n >= 64) ? 32 : (n / 2);
        bool t64 = (nchk > 0);
        for (int j = 0; j < nchk; j++)
            if (w[2 * j + 1] != 0) { t64 = false; break; }
        g_t64 = t64 ? 1 : 0;
    }
}

// ---------------- K1: fused per-row stats + hist1 + (last block) scan1 ------
__global__ __launch_bounds__(256) void k_main(const float* __restrict__ y1,
                                              const float* __restrict__ y2,
                                              const void*  __restrict__ targ,
                                              const void*  __restrict__ ep,
                                              int n) {
    int row  = blockIdx.x * 8 + (threadIdx.x >> 5);
    int lane = threadIdx.x & 31;
    __shared__ double skl[8], sls[8];

    double kl_i = 0.0, lossd = 0.0;

    if (row < n) {
        const float4 av = ((const float4*)(y1 + (size_t)row * C))[lane];
        const float4 bv = ((const float4*)(y2 + (size_t)row * C))[lane];
        float a[4] = {av.x, av.y, av.z, av.w};
        float b[4] = {bv.x, bv.y, bv.z, bv.w};

        float m1 = a[0], m2 = b[0];
        int   i1 = 0,   i2 = 0;
#pragma unroll
        for (int j = 1; j < 4; j++) {
            if (a[j] > m1) { m1 = a[j]; i1 = j; }
            if (b[j] > m2) { m2 = b[j]; i2 = j; }
        }
        i1 += lane * 4; i2 += lane * 4;

#pragma unroll
        for (int off = 16; off; off >>= 1) {
            float om = __shfl_xor_sync(FULL, m1, off);
            int   oi = __shfl_xor_sync(FULL, i1, off);
            if (om > m1 || (om == m1 && oi < i1)) { m1 = om; i1 = oi; }
            float pm = __shfl_xor_sync(FULL, m2, off);
            int   pi = __shfl_xor_sync(FULL, i2, off);
            if (pm > m2 || (pm == m2 && pi < i2)) { m2 = pm; i2 = pi; }
        }

        float s1 = 0.f, s2 = 0.f, w1 = 0.f, w2 = 0.f;
#pragma unroll
        for (int j = 0; j < 4; j++) {
            float d  = a[j] - b[j];
            float e1 = __expf(a[j] - m1);
            float e2 = __expf(b[j] - m2);
            s1 += e1; s2 += e2;
            w1 += e1 * d; w2 -= e2 * d;
        }
#pragma unroll
        for (int off = 16; off; off >>= 1) {
            s1 += __shfl_xor_sync(FULL, s1, off);
            s2 += __shfl_xor_sync(FULL, s2, off);
            w1 += __shfl_xor_sync(FULL, w1, off);
            w2 += __shfl_xor_sync(FULL, w2, off);
        }

        int t;
        if (g_t64) t = (int)(((const long long*)targ)[row]);
        else       t = ((const int*)targ)[row];
        int ts = t & 3, tl = t >> 2;
        float ca  = (ts == 0) ? a[0] : (ts == 1) ? a[1] : (ts == 2) ? a[2] : a[3];
        float cb  = (ts == 0) ? b[0] : (ts == 1) ? b[1] : (ts == 2) ? b[2] : b[3];
        float y1t = __shfl_sync(FULL, ca, tl);
        float y2t = __shfl_sync(FULL, cb, tl);

        int ps = i1 & 3, pl = i1 >> 2;
        float cbp = (ps == 0) ? b[0] : (ps == 1) ? b[1] : (ps == 2) ? b[2] : b[3];
        float y2p = __shfl_sync(FULL, cbp, pl);

        float ls1 = __logf(s1), ls2 = __logf(s2);
        float lse1 = m1 + ls1, lse2 = m2 + ls2;

        float loss = (lse1 - y1t) + (lse2 - y2t);
        lossd = (double)loss;
        kl_i  = (double)(w1 / s1) + (double)(w2 / s2);

        float pc   = 1.0f / (s1 * s2);
        float corr = -1.0f;
        if (i1 == i2 && pc > 0.5f)
            corr = sqrtf(pc) * (ls1 + (lse2 - y2p));

        if (lane == 0) {
            g_loss[row] = loss;
            g_corr[row] = corr;
            atomicAdd(&g_h1[orderf(loss) >> 21], 1u);   // fused hist1
        }
    }

    int wid = threadIdx.x >> 5;
    if (lane == 0) { skl[wid] = kl_i; sls[wid] = lossd; }
    __syncthreads();
    if (threadIdx.x == 0) {
        double ak = 0.0, al = 0.0;
#pragma unroll
        for (int w = 0; w < 8; w++) { ak += skl[w]; al += sls[w]; }
        int slot = blockIdx.x & 31;
        atomicAdd(&g_kl_part[slot], ak);
        atomicAdd(&g_loss_part[slot], al);
    }

    // last block performs scan1 (256 threads, parallel)
    if (last_block(&g_tick1)) {
        int epoch = *((const int*)ep);
        int k = num_remember_dev(epoch, n);
        if (k < 1) k = 1;
        g_krem = 1; g_b1 = 2047u;          // fallback
        __syncthreads();
        find_bucket<2048>(g_h1, k, &g_b1, &g_krem);
    }
}

// ---------------- hist2 + (last block) scan2 --------------------------------
__global__ __launch_bounds__(256) void k_hist2(int n) {
    __shared__ unsigned sh[2048];
    for (int i = threadIdx.x; i < 2048; i += blockDim.x) sh[i] = 0;
    __syncthreads();
    unsigned b1 = g_b1;
    int stride = blockDim.x * gridDim.x;
    for (int i = blockIdx.x * blockDim.x + threadIdx.x; i < n; i += stride) {
        unsigned u = orderf(g_loss[i]);
        if ((u >> 21) == b1) atomicAdd(&sh[(u >> 10) & 2047u], 1u);
    }
    __syncthreads();
    for (int i = threadIdx.x; i < 2048; i += blockDim.x)
        if (sh[i]) atomicAdd(&g_h2[i], sh[i]);

    if (last_block(&g_tick2)) {
        int k = g_krem;
        __shared__ unsigned sb; __shared__ int skr;
        if (threadIdx.x == 0) { sb = 2047u; skr = 1; }
        __syncthreads();
        find_bucket<2048>(g_h2, k, &sb, &skr);
        __syncthreads();
        if (threadIdx.x == 0) {
            g_b12 = (g_b1 << 11) | sb;
            g_krem = skr;
        }
    }
}

// ---------------- hist3 + (last block) scan3 --------------------------------
__global__ __launch_bounds__(256) void k_hist3(int n) {
    __shared__ unsigned sh[1024];
    for (int i = threadIdx.x; i < 1024; i += blockDim.x) sh[i] = 0;
    __syncthreads();
    unsigned b12 = g_b12;
    int stride = blockDim.x * gridDim.x;
    for (int i = blockIdx.x * blockDim.x + threadIdx.x; i < n; i += stride) {
        unsigned u = orderf(g_loss[i]);
        if ((u >> 10) == b12) atomicAdd(&sh[u & 1023u], 1u);
    }
    __syncthreads();
    for (int i = threadIdx.x; i < 1024; i += blockDim.x)
        if (sh[i]) atomicAdd(&g_h3[i], sh[i]);

    if (last_block(&g_tick3)) {
        int k = g_krem;
        __shared__ unsigned sb;
        if (threadIdx.x == 0) sb = 1023u;
        __syncthreads();
        int dummy;
        find_bucket<1024>(g_h3, k, &sb, &dummy);
        __syncthreads();
        if (threadIdx.x == 0) g_key = (g_b12 << 10) | sb;
    }
}

// ---------------- reduce + (last block) finalize ----------------------------
__global__ __launch_bounds__(256) void k_reduce(const void* __restrict__ ep,
                                                int n, float* __restrict__ out) {
    unsigned key = g_key;
    double cs = 0.0, crs = 0.0;
    unsigned long long cnt = 0ull;
    int stride = blockDim.x * gridDim.x;
    for (int i = blockIdx.x * blockDim.x + threadIdx.x; i < n; i += stride) {
        float L = g_loss[i];
        unsigned u = orderf(L);
        if (u <= key) {
            cs += (double)L;
        } else {
            float c = g_corr[i];
            if (c >= 0.0f) { crs += (double)c; cnt++; }
        }
    }
#pragma unroll
    for (int off = 16; off; off >>= 1) {
        cs  += __shfl_xor_sync(FULL, cs, off);
        crs += __shfl_xor_sync(FULL, crs, off);
        cnt += __shfl_xor_sync(FULL, cnt, off);
    }
    __shared__ double sc[8], sr[8];
    __shared__ unsigned long long sn[8];
    int lane = threadIdx.x & 31, wid = threadIdx.x >> 5;
    if (lane == 0) { sc[wid] = cs; sr[wid] = crs; sn[wid] = cnt; }
    __syncthreads();
    if (threadIdx.x == 0) {
        double a = 0.0, b = 0.0; unsigned long long c = 0ull;
#pragma unroll
        for (int w = 0; w < 8; w++) { a += sc[w]; b += sr[w]; c += sn[w]; }
        atomicAdd(&g_clean_sum, a);
        atomicAdd(&g_corr_sum, b);
        atomicAdd(&g_cnt, c);
    }

    if (last_block(&g_tick4)) {
        if (threadIdx.x == 0) {
            int epoch = *((const int*)ep);
            double klsum = 0.0, lsum = 0.0;
            for (int i = 0; i < 32; i++) { klsum += g_kl_part[i]; lsum += g_loss_part[i]; }
            double res;
            if (epoch == 0) {
                res = lsum / (double)n;
            } else {
                int k = num_remember_dev(epoch, n);
                if (k < 1) k = 1;
                double clean = g_clean_sum / (double)k;
                double corrm = (g_cnt > 0ull) ? (g_corr_sum / (double)g_cnt) : 0.0;
                res = clean + corrm + 0.1 * (klsum / (double)n);
            }
            *out = (float)res;
        }
    }
}

// ---------------- launch ------------------------------------------------------
extern "C" void kernel_launch(void* const* d_in, const int* in_sizes, int n_in,
                              void* d_out, int out_size) {
    const float* y1   = (const float*)d_in[0];
    const float* y2   = (const float*)d_in[1];
    const void*  targ = d_in[2];
    const void*  ep   = d_in[3];
    int n = in_sizes[0] / C;

    k_init<<<1, 1024>>>(targ, n);
    k_main<<<(n + 7) / 8, 256>>>(y1, y2, targ, ep, n);
    k_hist2<<<256, 256>>>(n);
    k_hist3<<<256, 256>>>(n);
    k_reduce<<<256, 256>>>(ep, n, (float*)d_out);
}

// round 13
// speedup vs baseline: 1.3536x; 1.0007x over previous
#include <cuda_runtime.h>

#define FULL 0xffffffffu

constexpr int C    = 128;
constexpr int NMAX = 262144;

// ---------------- device scratch (static: no allocation allowed) ------------
__device__ float    g_loss[NMAX];
__device__ float    g_corr[NMAX];          // corr value if masked, -1.0f sentinel otherwise
__device__ double   g_kl_part[32];
__device__ double   g_loss_part[32];
__device__ double   g_clean_sum;
__device__ double   g_corr_sum;
__device__ unsigned long long g_cnt;
__device__ unsigned g_h1[2048], g_h2[2048], g_h3[1024];
__device__ unsigned g_b1, g_b12, g_key;
__device__ int      g_krem;
__device__ int      g_t64;                 // 1 if targets are int64
__device__ unsigned g_tick1, g_tick2, g_tick3, g_tick4;

// float -> order-preserving uint
__device__ __forceinline__ unsigned orderf(float f) {
    unsigned u = __float_as_uint(f);
    return (u & 0x80000000u) ? ~u : (u | 0x80000000u);
}

__device__ __forceinline__ int num_remember_dev(int epoch, int n) {
    double fr = fmin(0.5, (0.5 / 100.0) * (double)epoch);
    double rr = fmax(0.5, 1.0 - fr);
    return (int)(rr * (double)n);
}

// parallel "find bucket where cumsum crosses k" — call with 256 threads,
// NB buckets (multiple of 256). Exactly one thread hits the crossing.
template <int NB>
__device__ __forceinline__ void find_bucket(const unsigned* __restrict__ hist, int k,
                                            unsigned* out_b, int* out_krem) {
    __shared__ unsigned csum[256];
    constexpr int PER = NB / 256;
    int t = threadIdx.x;
    unsigned loc[PER];
    unsigned s = 0;
#pragma unroll
    for (int j = 0; j < PER; j++) { loc[j] = hist[t * PER + j]; s += loc[j]; }
    csum[t] = s;
    __syncthreads();
    // inclusive Hillis-Steele scan over 256 chunk sums
#pragma unroll
    for (int off = 1; off < 256; off <<= 1) {
        unsigned v = (t >= off) ? csum[t - off] : 0u;
        __syncthreads();
        csum[t] += v;
        __syncthreads();
    }
    unsigned prev = (t == 0) ? 0u : csum[t - 1];
    if (prev < (unsigned)k && csum[t] >= (unsigned)k) {
        unsigned cum = prev;
#pragma unroll
        for (int j = 0; j < PER; j++) {
            unsigned c = loc[j];
            if (cum + c >= (unsigned)k) { *out_b = (unsigned)(t * PER + j); *out_krem = k - (int)cum; break; }
            cum += c;
        }
    }
}

// returns true for the last block to arrive (block-uniform)
__device__ __forceinline__ bool last_block(unsigned* tick) {
    __threadfence();
    __shared__ bool isLast;
    if (threadIdx.x == 0) isLast = (atomicAdd(tick, 1u) == gridDim.x - 1);
    __syncthreads();
    return isLast;
}

// ---------------- K0: zero accumulators + detect int64 targets --------------
__global__ void k_init(const void* __restrict__ targ, int n) {
    int t = threadIdx.x;
    for (int i = t; i < 2048; i += 1024) g_h1[i] = 0;
    for (int i = t; i < 2048; i += 1024) g_h2[i] = 0;
    for (int i = t; i < 1024; i += 1024) g_h3[i] = 0;
    if (t < 32) { g_kl_part[t] = 0.0; g_loss_part[t] = 0.0; }
    if (t == 0) {
        g_clean_sum = 0.0; g_corr_sum = 0.0; g_cnt = 0ull;
        g_b1 = 0; g_b12 = 0; g_key = 0; g_krem = 1;
        g_tick1 = 0; g_tick2 = 0; g_tick3 = 0; g_tick4 = 0;
        const int* w = (const int*)targ;
        int nchk = (n >= 64) ? 32 : (n / 2);
        bool t64 = (nchk > 0);
        for (int j = 0; j < nchk; j++)
            if (w[2 * j + 1] != 0) { t64 = false; break; }
        g_t64 = t64 ? 1 : 0;
    }
}

// ---------------- K1: fused per-row stats + hist1 + (last block) scan1 ------
__global__ __launch_bounds__(256) void k_main(const float* __restrict__ y1,
                                              const float* __restrict__ y2,
                                              const void*  __restrict__ targ,
                                              const void*  __restrict__ ep,
                                              int n) {
    int row  = blockIdx.x * 8 + (threadIdx.x >> 5);
    int lane = threadIdx.x & 31;
    __shared__ double skl[8], sls[8];

    double kl_i = 0.0, lossd = 0.0;

    if (row < n) {
        const float4 av = ((const float4*)(y1 + (size_t)row * C))[lane];
        const float4 bv = ((const float4*)(y2 + (size_t)row * C))[lane];
        float a[4] = {av.x, av.y, av.z, av.w};
        float b[4] = {bv.x, bv.y, bv.z, bv.w};

        float m1 = a[0], m2 = b[0];
        int   i1 = 0,   i2 = 0;
#pragma unroll
        for (int j = 1; j < 4; j++) {
            if (a[j] > m1) { m1 = a[j]; i1 = j; }
            if (b[j] > m2) { m2 = b[j]; i2 = j; }
        }
        i1 += lane * 4; i2 += lane * 4;

#pragma unroll
        for (int off = 16; off; off >>= 1) {
            float om = __shfl_xor_sync(FULL, m1, off);
            int   oi = __shfl_xor_sync(FULL, i1, off);
            if (om > m1 || (om == m1 && oi < i1)) { m1 = om; i1 = oi; }
            float pm = __shfl_xor_sync(FULL, m2, off);
            int   pi = __shfl_xor_sync(FULL, i2, off);
            if (pm > m2 || (pm == m2 && pi < i2)) { m2 = pm; i2 = pi; }
        }

        float s1 = 0.f, s2 = 0.f, w1 = 0.f, w2 = 0.f;
#pragma unroll
        for (int j = 0; j < 4; j++) {
            float d  = a[j] - b[j];
            float e1 = __expf(a[j] - m1);
            float e2 = __expf(b[j] - m2);
            s1 += e1; s2 += e2;
            w1 += e1 * d; w2 -= e2 * d;
        }
#pragma unroll
        for (int off = 16; off; off >>= 1) {
            s1 += __shfl_xor_sync(FULL, s1, off);
            s2 += __shfl_xor_sync(FULL, s2, off);
            w1 += __shfl_xor_sync(FULL, w1, off);
            w2 += __shfl_xor_sync(FULL, w2, off);
        }

        int t;
        if (g_t64) t = (int)(((const long long*)targ)[row]);
        else       t = ((const int*)targ)[row];
        int ts = t & 3, tl = t >> 2;
        float ca  = (ts == 0) ? a[0] : (ts == 1) ? a[1] : (ts == 2) ? a[2] : a[3];
        float cb  = (ts == 0) ? b[0] : (ts == 1) ? b[1] : (ts == 2) ? b[2] : b[3];
        float y1t = __shfl_sync(FULL, ca, tl);
        float y2t = __shfl_sync(FULL, cb, tl);

        int ps = i1 & 3, pl = i1 >> 2;
        float cbp = (ps == 0) ? b[0] : (ps == 1) ? b[1] : (ps == 2) ? b[2] : b[3];
        float y2p = __shfl_sync(FULL, cbp, pl);

        float ls1 = __logf(s1), ls2 = __logf(s2);
        float lse1 = m1 + ls1, lse2 = m2 + ls2;

        float loss = (lse1 - y1t) + (lse2 - y2t);
        lossd = (double)loss;
        kl_i  = (double)(w1 / s1) + (double)(w2 / s2);

        float pc   = 1.0f / (s1 * s2);
        float corr = -1.0f;
        if (i1 == i2 && pc > 0.5f)
            corr = sqrtf(pc) * (ls1 + (lse2 - y2p));

        if (lane == 0) {
            g_loss[row] = loss;
            g_corr[row] = corr;
            atomicAdd(&g_h1[orderf(loss) >> 21], 1u);   // fused hist1
        }
    }

    int wid = threadIdx.x >> 5;
    if (lane == 0) { skl[wid] = kl_i; sls[wid] = lossd; }
    __syncthreads();
    if (threadIdx.x == 0) {
        double ak = 0.0, al = 0.0;
#pragma unroll
        for (int w = 0; w < 8; w++) { ak += skl[w]; al += sls[w]; }
        int slot = blockIdx.x & 31;
        atomicAdd(&g_kl_part[slot], ak);
        atomicAdd(&g_loss_part[slot], al);
    }

    // last block performs scan1 (256 threads, parallel)
    if (last_block(&g_tick1)) {
        int epoch = *((const int*)ep);
        int k = num_remember_dev(epoch, n);
        if (k < 1) k = 1;
        g_krem = 1; g_b1 = 2047u;          // fallback
        __syncthreads();
        find_bucket<2048>(g_h1, k, &g_b1, &g_krem);
    }
}

// ---------------- hist2 + (last block) scan2 --------------------------------
__global__ __launch_bounds__(256) void k_hist2(int n) {
    __shared__ unsigned sh[2048];
    for (int i = threadIdx.x; i < 2048; i += blockDim.x) sh[i] = 0;
    __syncthreads();
    unsigned b1 = g_b1;
    int stride = blockDim.x * gridDim.x;
    for (int i = blockIdx.x * blockDim.x + threadIdx.x; i < n; i += stride) {
        unsigned u = orderf(g_loss[i]);
        if ((u >> 21) == b1) atomicAdd(&sh[(u >> 10) & 2047u], 1u);
    }
    __syncthreads();
    for (int i = threadIdx.x; i < 2048; i += blockDim.x)
        if (sh[i]) atomicAdd(&g_h2[i], sh[i]);

    if (last_block(&g_tick2)) {
        int k = g_krem;
        __shared__ unsigned sb; __shared__ int skr;
        if (threadIdx.x == 0) { sb = 2047u; skr = 1; }
        __syncthreads();
        find_bucket<2048>(g_h2, k, &sb, &skr);
        __syncthreads();
        if (threadIdx.x == 0) {
            g_b12 = (g_b1 << 11) | sb;
            g_krem = skr;
        }
    }
}

// ---------------- hist3 + (last block) scan3 --------------------------------
__global__ __launch_bounds__(256) void k_hist3(int n) {
    __shared__ unsigned sh[1024];
    for (int i = threadIdx.x; i < 1024; i += blockDim.x) sh[i] = 0;
    __syncthreads();
    unsigned b12 = g_b12;
    int stride = blockDim.x * gridDim.x;
    for (int i = blockIdx.x * blockDim.x + threadIdx.x; i < n; i += stride) {
        unsigned u = orderf(g_loss[i]);
        if ((u >> 10) == b12) atomicAdd(&sh[u & 1023u], 1u);
    }
    __syncthreads();
    for (int i = threadIdx.x; i < 1024; i += blockDim.x)
        if (sh[i]) atomicAdd(&g_h3[i], sh[i]);

    if (last_block(&g_tick3)) {
        int k = g_krem;
        __shared__ unsigned sb;
        if (threadIdx.x == 0) sb = 1023u;
        __syncthreads();
        int dummy;
        find_bucket<1024>(g_h3, k, &sb, &dummy);
        __syncthreads();
        if (threadIdx.x == 0) g_key = (g_b12 << 10) | sb;
    }
}

// ---------------- reduce + (last block) finalize ----------------------------
__global__ __launch_bounds__(256) void k_reduce(const void* __restrict__ ep,
                                                int n, float* __restrict__ out) {
    unsigned key = g_key;
    double cs = 0.0, crs = 0.0;
    unsigned long long cnt = 0ull;
    int stride = blockDim.x * gridDim.x;
    for (int i = blockIdx.x * blockDim.x + threadIdx.x; i < n; i += stride) {
        float L = g_loss[i];
        unsigned u = orderf(L);
        if (u <= key) {
            cs += (double)L;
        } else {
            float c = g_corr[i];
            if (c >= 0.0f) { crs += (double)c; cnt++; }
        }
    }
#pragma unroll
    for (int off = 16; off; off >>= 1) {
        cs  += __shfl_xor_sync(FULL, cs, off);
        crs += __shfl_xor_sync(FULL, crs, off);
        cnt += __shfl_xor_sync(FULL, cnt, off);
    }
    __shared__ double sc[8], sr[8];
    __shared__ unsigned long long sn[8];
    int lane = threadIdx.x & 31, wid = threadIdx.x >> 5;
    if (lane == 0) { sc[wid] = cs; sr[wid] = crs; sn[wid] = cnt; }
    __syncthreads();
    if (threadIdx.x == 0) {
        double a = 0.0, b = 0.0; unsigned long long c = 0ull;
#pragma unroll
        for (int w = 0; w < 8; w++) { a += sc[w]; b += sr[w]; c += sn[w]; }
        atomicAdd(&g_clean_sum, a);
        atomicAdd(&g_corr_sum, b);
        atomicAdd(&g_cnt, c);
    }

    if (last_block(&g_tick4)) {
        if (threadIdx.x == 0) {
            int epoch = *((const int*)ep);
            double klsum = 0.0, lsum = 0.0;
            for (int i = 0; i < 32; i++) { klsum += g_kl_part[i]; lsum += g_loss_part[i]; }
            double res;
            if (epoch == 0) {
                res = lsum / (double)n;
            } else {
                int k = num_remember_dev(epoch, n);
                if (k < 1) k = 1;
                double clean = g_clean_sum / (double)k;
                double corrm = (g_cnt > 0ull) ? (g_corr_sum / (double)g_cnt) : 0.0;
                res = clean + corrm + 0.1 * (klsum / (double)n);
            }
            *out = (float)res;
        }
    }
}

// ---------------- launch ------------------------------------------------------
extern "C" void kernel_launch(void* const* d_in, const int* in_sizes, int n_in,
                              void* d_out, int out_size) {
    const float* y1   = (const float*)d_in[0];
    const float* y2   = (const float*)d_in[1];
    const void*  targ = d_in[2];
    const void*  ep   = d_in[3];
    int n = in_sizes[0] / C;

    k_init<<<1, 1024>>>(targ, n);
    k_main<<<(n + 7) / 8, 256>>>(y1, y2, targ, ep, n);
    k_hist2<<<256, 256>>>(n);
    k_hist3<<<256, 256>>>(n);
    k_reduce<<<256, 256>>>(ep, n, (float*)d_out);
}